// round 1
// baseline (speedup 1.0000x reference)
#include <cuda_runtime.h>
#include <math.h>

// gdfn_region_batch: fused single-kernel implementation.
// Inputs (metadata order): img[8,3,512,512]f32, noise[8,3,514,514]f32,
//   re_mask[8,3,512,512]f32, sel[8], mix_sel[8]  -> out[8,3,512,512]f32

#define BATCH 8
#define CH 3
#define HH 512
#define WW 512
#define HP 514          // H + 2*OFF
#define TS 32           // output tile
#define PR 38           // TS + 6  (img_p region)
#define E2 36           // TS + 4  (img_r region)
#define E1 34           // TS + 2  (ids / img_3d_mod region)
#define NTHREADS 256

#define SP_SIZE  (CH*PR*PR)   // 4332 floats
#define SR_SIZE  (E2*E2)      // 1296
#define S3D_SIZE (E1*E1*9)    // 10404
#define SMOD_SIZE (E2*E2)     // 1296
#define SMEM_FLOATS (SP_SIZE + SR_SIZE + S3D_SIZE + SMOD_SIZE)  // 17328 -> 69312 B

__global__ __launch_bounds__(NTHREADS)
void gdfn_kernel(const float* __restrict__ img,
                 const float* __restrict__ noise,
                 const float* __restrict__ re_mask,
                 const int*   __restrict__ sel,
                 const int*   __restrict__ mix_sel,
                 float* __restrict__ out)
{
    const int b  = blockIdx.z;
    const int h0 = blockIdx.y * TS;
    const int w0 = blockIdx.x * TS;
    const int tid = threadIdx.x;

    const bool apply = (sel[b] != 0);

    // ---- fast-path detection -------------------------------------------------
    // If !apply, out = img (exact). If apply but re_mask is all-ones on this
    // tile, out = img_mod*(1-1) + img*1 = img exactly as well. Both -> copy.
    int local_ok = 1;
    if (apply) {
        for (int i = tid; i < CH * TS * TS; i += NTHREADS) {
            int c  = i / (TS * TS);
            int r  = (i / TS) % TS;
            int cc = i % TS;
            float rm = re_mask[(((size_t)b * CH + c) * HH + (h0 + r)) * WW + (w0 + cc)];
            if (rm != 1.0f) local_ok = 0;
        }
    }
    int allone = __syncthreads_and(local_ok);
    if (!apply || allone) {
        // copy img tile -> out (float4, tiles are 16B-aligned: w0 multiple of 32)
        for (int i = tid; i < CH * TS * (TS / 4); i += NTHREADS) {
            int c   = i / (TS * TS / 4);
            int rem = i % (TS * TS / 4);
            int r   = rem / (TS / 4);
            int q   = rem % (TS / 4);
            size_t base = (((size_t)b * CH + c) * HH + (h0 + r)) * WW + w0 + q * 4;
            *(float4*)(out + base) = *(const float4*)(img + base);
        }
        return;
    }

    // ---- heavy path ----------------------------------------------------------
    extern __shared__ float smem[];
    float* sp   = smem;                    // [CH][PR][PR] img_p = pad(img)+noise
    float* sr   = sp + SP_SIZE;            // [E2][E2]     img_r (0 outside image)
    float* s3d  = sr + SR_SIZE;            // [E1][E1][9]  img_3d (min over c)
    float* smod = s3d + S3D_SIZE;          // [E2][E2]     img_3d_mod (0 outside)

    // Phase 1: build img_p region.  img_p coords y,x in [0,514).
    for (int i = tid; i < CH * PR * PR; i += NTHREADS) {
        int c   = i / (PR * PR);
        int rem = i % (PR * PR);
        int py  = rem / PR, px = rem % PR;
        int y = h0 - 2 + py;
        int x = w0 - 2 + px;
        float v = 0.0f;
        if (y >= 0 && y < HP && x >= 0 && x < HP) {
            v = noise[(((size_t)b * CH + c) * HP + y) * HP + x];
            int iy = y - 1, ix = x - 1;
            if (iy >= 0 && iy < HH && ix >= 0 && ix < WW)
                v += img[(((size_t)b * CH + c) * HH + iy) * WW + ix];
        }
        sp[(c * PR + py) * PR + px] = v;
    }
    __syncthreads();

    const bool mix = (mix_sel[b] != 0);

    // Phase 2: img_r on E2 x E2 region; also img_3d (m[9]) into s3d for inner E1 x E1.
    for (int p = tid; p < E2 * E2; p += NTHREADS) {
        int r  = p / E2, cc = p % E2;
        int gy = h0 - 2 + r, gx = w0 - 2 + cc;
        float img_r = 0.0f;
        if (gy >= 0 && gy < HH && gx >= 0 && gx < WW) {
            float m[9], vsum[9];
            #pragma unroll
            for (int k = 0; k < 9; k++) { m[k] = 3.4e38f; vsum[k] = 0.0f; }
            #pragma unroll
            for (int c = 0; c < CH; c++) {
                float v[9]; float s = 0.0f;
                #pragma unroll
                for (int i = 0; i < 3; i++)
                    #pragma unroll
                    for (int j = 0; j < 3; j++) {
                        float t = sp[(c * PR + r + i) * PR + cc + j];
                        v[i * 3 + j] = t; s += t; vsum[i * 3 + j] += t;
                    }
                float mean = s * (1.0f / 9.0f);
                float sd2 = 0.0f;
                #pragma unroll
                for (int k = 0; k < 9; k++) {
                    float d = v[k] - mean; v[k] = d; sd2 += d * d;
                }
                // var(ddof=1) = sd2/8 ; exponent = -d^2 / (2*var) = -d^2 * 4/sd2
                float inv = __fdividef(4.0f, sd2);
                #pragma unroll
                for (int k = 0; k < 9; k++) {
                    float wv = __expf(-v[k] * v[k] * inv);
                    m[k] = fminf(m[k], wv);
                }
            }
            float num = 0.0f, den = 0.0f;
            #pragma unroll
            for (int k = 0; k < 9; k++) { num += m[k] * vsum[k]; den += m[k]; }
            img_r = __fdividef(num, den);
            if (r >= 1 && r < E2 - 1 && cc >= 1 && cc < E2 - 1) {
                int q = ((r - 1) * E1 + (cc - 1)) * 9;
                #pragma unroll
                for (int k = 0; k < 9; k++) s3d[q + k] = m[k];
            }
        }
        sr[r * E2 + cc] = img_r;
    }
    __syncthreads();

    // Phase 3: argmin/argmax of 3x3 img_r window (first-index tie-break, like jnp),
    //          gather img_3d -> img_3d_mod on E1 x E1 region.
    for (int p = tid; p < E1 * E1; p += NTHREADS) {
        int r  = 1 + p / E1, cc = 1 + p % E1;
        int gy = h0 - 2 + r, gx = w0 - 2 + cc;
        float mv = 0.0f;
        if (gy >= 0 && gy < HH && gx >= 0 && gx < WW) {
            float bmin = 3.4e38f, bmax = -3.4e38f;
            int kmin = 0, kmax = 0;
            #pragma unroll
            for (int i = 0; i < 3; i++)
                #pragma unroll
                for (int j = 0; j < 3; j++) {
                    float val = sr[(r - 1 + i) * E2 + (cc - 1 + j)];
                    int k = i * 3 + j;
                    if (val < bmin) { bmin = val; kmin = k; }
                    if (val > bmax) { bmax = val; kmax = k; }
                }
            int id = mix ? kmax : kmin;
            mv = s3d[((r - 1) * E1 + (cc - 1)) * 9 + id];
        }
        smod[r * E2 + cc] = mv;
    }
    __syncthreads();

    // Phase 4: img_mod and final compose for the TS x TS tile.
    for (int p = tid; p < TS * TS; p += NTHREADS) {
        int ty = p / TS, tx = p % TS;
        int gy = h0 + ty, gx = w0 + tx;
        float mm[9]; float den = 0.0f;
        #pragma unroll
        for (int i = 0; i < 3; i++)
            #pragma unroll
            for (int j = 0; j < 3; j++) {
                float t = smod[(ty + 1 + i) * E2 + (tx + 1 + j)];
                mm[i * 3 + j] = t; den += t;
            }
        float rden = __fdividef(1.0f, den);
        #pragma unroll
        for (int c = 0; c < CH; c++) {
            float num = 0.0f;
            #pragma unroll
            for (int i = 0; i < 3; i++)
                #pragma unroll
                for (int j = 0; j < 3; j++)
                    num += sp[(c * PR + ty + 2 + i) * PR + tx + 2 + j] * mm[i * 3 + j];
            float imod = num * rden;
            size_t gidx = (((size_t)b * CH + c) * HH + gy) * WW + gx;
            float im = img[gidx];
            float re = re_mask[gidx];
            // exact form: where re==1 this yields im bit-exactly, like the reference
            out[gidx] = imod * (1.0f - re) + im * re;
        }
    }
}

extern "C" void kernel_launch(void* const* d_in, const int* in_sizes, int n_in,
                              void* d_out, int out_size)
{
    const float* img     = (const float*)d_in[0];
    const float* noise   = (const float*)d_in[1];
    const float* re_mask = (const float*)d_in[2];
    const int*   sel     = (const int*)d_in[3];
    const int*   mix_sel = (const int*)d_in[4];
    float* out = (float*)d_out;

    size_t smem = SMEM_FLOATS * sizeof(float);   // 69312 B > 48KB -> opt in
    cudaFuncSetAttribute(gdfn_kernel,
                         cudaFuncAttributeMaxDynamicSharedMemorySize, (int)smem);

    dim3 grid(WW / TS, HH / TS, BATCH);
    gdfn_kernel<<<grid, NTHREADS, smem>>>(img, noise, re_mask, sel, mix_sel, out);
}

// round 2
// speedup vs baseline: 1.2279x; 1.2279x over previous
#include <cuda_runtime.h>
#include <math.h>

// gdfn_region_batch: split copy/flag kernel (no smem, full occupancy) +
// compacted heavy-tile kernel (69KB smem, all real work starts wave 1).

#define BATCH 8
#define CH 3
#define HH 512
#define WW 512
#define HP 514
#define TS 32
#define PR 38          // TS + 6
#define E2 36          // TS + 4
#define E1 34          // TS + 2
#define NTHREADS 256
#define NTILES (BATCH * (HH/TS) * (WW/TS))   // 2048

#define SP_SIZE  (CH*PR*PR)
#define SR_SIZE  (E2*E2)
#define S3D_SIZE (E1*E1*9)
#define SMOD_SIZE (E2*E2)
#define SMEM_FLOATS (SP_SIZE + SR_SIZE + S3D_SIZE + SMOD_SIZE)  // 17328 floats

__device__ int g_heavy_count;
__device__ int g_heavy_list[NTILES];

__global__ void reset_kernel() { g_heavy_count = 0; }

// ---------------------------------------------------------------------------
// Kernel 1: detect heavy tiles, copy all non-heavy tiles. Zero smem.
// ---------------------------------------------------------------------------
__global__ __launch_bounds__(NTHREADS)
void copy_flag_kernel(const float* __restrict__ img,
                      const float* __restrict__ re_mask,
                      const int*   __restrict__ sel,
                      float* __restrict__ out)
{
    const int b  = blockIdx.z;
    const int h0 = blockIdx.y * TS;
    const int w0 = blockIdx.x * TS;
    const int tid = threadIdx.x;

    const bool apply = (sel[b] != 0);

    int local_ok = 1;
    if (apply) {
        // scan re_mask tile (float4): 3*32*8 = 768 vec4 loads / 256 threads
        for (int i = tid; i < CH * TS * (TS / 4); i += NTHREADS) {
            int c   = i / (TS * TS / 4);
            int rem = i % (TS * TS / 4);
            int r   = rem / (TS / 4);
            int q   = rem % (TS / 4);
            size_t base = (((size_t)b * CH + c) * HH + (h0 + r)) * WW + w0 + q * 4;
            float4 rm = *(const float4*)(re_mask + base);
            if (rm.x != 1.0f || rm.y != 1.0f || rm.z != 1.0f || rm.w != 1.0f)
                local_ok = 0;
        }
    }
    int allone = __syncthreads_and(local_ok);
    bool heavy = apply && !allone;

    if (heavy) {
        if (tid == 0) {
            int slot = atomicAdd(&g_heavy_count, 1);
            g_heavy_list[slot] = (b << 8) | (blockIdx.y << 4) | blockIdx.x;
        }
        return;  // heavy kernel writes this tile entirely
    }

    // copy img tile -> out
    for (int i = tid; i < CH * TS * (TS / 4); i += NTHREADS) {
        int c   = i / (TS * TS / 4);
        int rem = i % (TS * TS / 4);
        int r   = rem / (TS / 4);
        int q   = rem % (TS / 4);
        size_t base = (((size_t)b * CH + c) * HH + (h0 + r)) * WW + w0 + q * 4;
        *(float4*)(out + base) = *(const float4*)(img + base);
    }
}

// ---------------------------------------------------------------------------
// Kernel 2: heavy tiles only (compacted worklist).
// ---------------------------------------------------------------------------
__global__ __launch_bounds__(NTHREADS)
void heavy_kernel(const float* __restrict__ img,
                  const float* __restrict__ noise,
                  const float* __restrict__ re_mask,
                  const int*   __restrict__ mix_sel,
                  float* __restrict__ out)
{
    if ((int)blockIdx.x >= g_heavy_count) return;
    const int t  = g_heavy_list[blockIdx.x];
    const int b  = t >> 8;
    const int h0 = ((t >> 4) & 15) * TS;
    const int w0 = (t & 15) * TS;
    const int tid = threadIdx.x;

    extern __shared__ float smem[];
    float* sp   = smem;                    // [CH][PR][PR] img_p = pad(img)+noise
    float* sr   = sp + SP_SIZE;            // [E2][E2]     img_r
    float* s3d  = sr + SR_SIZE;            // [E1][E1][9]  img_3d (min over c)
    float* smod = s3d + S3D_SIZE;          // [E2][E2]     img_3d_mod

    // Phase 1: img_p region
    for (int i = tid; i < CH * PR * PR; i += NTHREADS) {
        int c   = i / (PR * PR);
        int rem = i % (PR * PR);
        int py  = rem / PR, px = rem % PR;
        int y = h0 - 2 + py;
        int x = w0 - 2 + px;
        float v = 0.0f;
        if (y >= 0 && y < HP && x >= 0 && x < HP) {
            v = noise[(((size_t)b * CH + c) * HP + y) * HP + x];
            int iy = y - 1, ix = x - 1;
            if (iy >= 0 && iy < HH && ix >= 0 && ix < WW)
                v += img[(((size_t)b * CH + c) * HH + iy) * WW + ix];
        }
        sp[(c * PR + py) * PR + px] = v;
    }
    __syncthreads();

    const bool mix = (mix_sel[b] != 0);

    // Phase 2: img_r on E2 x E2; img_3d into s3d for inner E1 x E1
    for (int p = tid; p < E2 * E2; p += NTHREADS) {
        int r  = p / E2, cc = p % E2;
        int gy = h0 - 2 + r, gx = w0 - 2 + cc;
        float img_r = 0.0f;
        if (gy >= 0 && gy < HH && gx >= 0 && gx < WW) {
            float m[9], vsum[9];
            #pragma unroll
            for (int k = 0; k < 9; k++) { m[k] = 3.4e38f; vsum[k] = 0.0f; }
            #pragma unroll
            for (int c = 0; c < CH; c++) {
                float v[9]; float s = 0.0f;
                #pragma unroll
                for (int i = 0; i < 3; i++)
                    #pragma unroll
                    for (int j = 0; j < 3; j++) {
                        float tv = sp[(c * PR + r + i) * PR + cc + j];
                        v[i * 3 + j] = tv; s += tv; vsum[i * 3 + j] += tv;
                    }
                float mean = s * (1.0f / 9.0f);
                float sd2 = 0.0f;
                #pragma unroll
                for (int k = 0; k < 9; k++) {
                    float d = v[k] - mean; v[k] = d; sd2 += d * d;
                }
                float inv = __fdividef(4.0f, sd2);   // = 1/(2*var_ddof1)
                #pragma unroll
                for (int k = 0; k < 9; k++) {
                    float wv = __expf(-v[k] * v[k] * inv);
                    m[k] = fminf(m[k], wv);
                }
            }
            float num = 0.0f, den = 0.0f;
            #pragma unroll
            for (int k = 0; k < 9; k++) { num += m[k] * vsum[k]; den += m[k]; }
            img_r = __fdividef(num, den);
            if (r >= 1 && r < E2 - 1 && cc >= 1 && cc < E2 - 1) {
                int q = ((r - 1) * E1 + (cc - 1)) * 9;
                #pragma unroll
                for (int k = 0; k < 9; k++) s3d[q + k] = m[k];
            }
        }
        sr[r * E2 + cc] = img_r;
    }
    __syncthreads();

    // Phase 3: argmin/argmax of img_r 3x3 (first-index tie-break), gather
    for (int p = tid; p < E1 * E1; p += NTHREADS) {
        int r  = 1 + p / E1, cc = 1 + p % E1;
        int gy = h0 - 2 + r, gx = w0 - 2 + cc;
        float mv = 0.0f;
        if (gy >= 0 && gy < HH && gx >= 0 && gx < WW) {
            float bmin = 3.4e38f, bmax = -3.4e38f;
            int kmin = 0, kmax = 0;
            #pragma unroll
            for (int i = 0; i < 3; i++)
                #pragma unroll
                for (int j = 0; j < 3; j++) {
                    float val = sr[(r - 1 + i) * E2 + (cc - 1 + j)];
                    int k = i * 3 + j;
                    if (val < bmin) { bmin = val; kmin = k; }
                    if (val > bmax) { bmax = val; kmax = k; }
                }
            int id = mix ? kmax : kmin;
            mv = s3d[((r - 1) * E1 + (cc - 1)) * 9 + id];
        }
        smod[r * E2 + cc] = mv;
    }
    __syncthreads();

    // Phase 4: img_mod and final compose
    for (int p = tid; p < TS * TS; p += NTHREADS) {
        int ty = p / TS, tx = p % TS;
        int gy = h0 + ty, gx = w0 + tx;
        float mm[9]; float den = 0.0f;
        #pragma unroll
        for (int i = 0; i < 3; i++)
            #pragma unroll
            for (int j = 0; j < 3; j++) {
                float tv = smod[(ty + 1 + i) * E2 + (tx + 1 + j)];
                mm[i * 3 + j] = tv; den += tv;
            }
        float rden = __fdividef(1.0f, den);
        #pragma unroll
        for (int c = 0; c < CH; c++) {
            float num = 0.0f;
            #pragma unroll
            for (int i = 0; i < 3; i++)
                #pragma unroll
                for (int j = 0; j < 3; j++)
                    num += sp[(c * PR + ty + 2 + i) * PR + tx + 2 + j] * mm[i * 3 + j];
            float imod = num * rden;
            size_t gidx = (((size_t)b * CH + c) * HH + gy) * WW + gx;
            float im = img[gidx];
            float re = re_mask[gidx];
            out[gidx] = imod * (1.0f - re) + im * re;  // exact where re==1
        }
    }
}

extern "C" void kernel_launch(void* const* d_in, const int* in_sizes, int n_in,
                              void* d_out, int out_size)
{
    const float* img     = (const float*)d_in[0];
    const float* noise   = (const float*)d_in[1];
    const float* re_mask = (const float*)d_in[2];
    const int*   sel     = (const int*)d_in[3];
    const int*   mix_sel = (const int*)d_in[4];
    float* out = (float*)d_out;

    size_t smem = SMEM_FLOATS * sizeof(float);
    cudaFuncSetAttribute(heavy_kernel,
                         cudaFuncAttributeMaxDynamicSharedMemorySize, (int)smem);

    reset_kernel<<<1, 1>>>();
    dim3 grid(WW / TS, HH / TS, BATCH);
    copy_flag_kernel<<<grid, NTHREADS>>>(img, re_mask, sel, out);
    heavy_kernel<<<NTILES, NTHREADS, smem>>>(img, noise, re_mask, mix_sel, out);
}